// round 5
// baseline (speedup 1.0000x reference)
#include <cuda_runtime.h>
#include <cuda_bf16.h>
#include <cstdint>
#include <math.h>

#define NN 8192
#define DD 128
#define NCHUNK 1056          // sum over bi of ceil((64-bi)/2)
#define COEF (10.0f/7.0f)
#define EXS 14.4269504089f   // 10 * log2(e)

__device__ __align__(16) __nv_bfloat16 g_featsb[(size_t)NN * DD];
__device__ float g_Et[NN];           // sum_all exp(l)  (incl. self)
__device__ float g_E1[NN];           // sum_{lab_j=1} exp(l)
__device__ float g_upart[64 * 256];  // per-prep-CTA class sums (128 x c0, 128 x c1)
__device__ int   g_c0part[64];

__device__ __forceinline__ uint32_t smem_u32(const void* p) {
    uint32_t a;
    asm("{ .reg .u64 t; cvta.to.shared.u64 t, %1; cvt.u32.u64 %0, t; }" : "=r"(a) : "l"(p));
    return a;
}
__device__ __forceinline__ float ex2f(float x) {
    float y; asm("ex2.approx.ftz.f32 %0, %1;" : "=f"(y) : "f"(x)); return y;
}
__device__ __forceinline__ void ldmx4(uint32_t* r, uint32_t addr) {
    asm volatile("ldmatrix.sync.aligned.m8n8.x4.shared.b16 {%0,%1,%2,%3}, [%4];"
                 : "=r"(r[0]), "=r"(r[1]), "=r"(r[2]), "=r"(r[3]) : "r"(addr));
}
__device__ __forceinline__ void mma16816(float* c, const uint32_t* a, const uint32_t* b) {
    asm volatile(
        "mma.sync.aligned.m16n8k16.row.col.f32.bf16.bf16.f32 "
        "{%0,%1,%2,%3}, {%4,%5,%6,%7}, {%8,%9}, {%0,%1,%2,%3};"
        : "+f"(c[0]), "+f"(c[1]), "+f"(c[2]), "+f"(c[3])
        : "r"(a[0]), "r"(a[1]), "r"(a[2]), "r"(a[3]), "r"(b[0]), "r"(b[1]));
}

#define SROW 272
#define SM_A   0
#define SM_B0  34816
#define SM_B1  69632
#define SM_RED 104448        // 256 floats
#define SM_TOTAL 105472

// ---- prep: f32->bf16 convert, class sums u_c, class counts, zero E accs, zero out
__global__ __launch_bounds__(512) void prep_kernel(const float* __restrict__ feats,
                                                   const int* __restrict__ labels,
                                                   float* __restrict__ out, int out_size) {
    __shared__ float s0[512], s1[512];
    __shared__ int slab[128];
    __shared__ int scnt;
    const int row0 = blockIdx.x * 128;
    const int t = threadIdx.x, k = t & 127, rg = t >> 7;

    if (t < 128) slab[t] = labels[row0 + t] != 0;
    if (t == 0) scnt = 0;
    __syncthreads();

    float a0 = 0.0f, a1 = 0.0f;
#pragma unroll 4
    for (int rr = 0; rr < 32; rr++) {
        int rloc = rg * 32 + rr;
        int r = row0 + rloc;
        float v = feats[(size_t)r * DD + k];
        __nv_bfloat16 b = __float2bfloat16(v);
        g_featsb[(size_t)r * DD + k] = b;
        float vb = __bfloat162float(b);
        if (slab[rloc]) a1 += vb; else a0 += vb;
    }
    s0[t] = a0; s1[t] = a1;

    if (t < 128) {
        unsigned bl = __ballot_sync(0xffffffffu, slab[t] == 0);
        if ((t & 31) == 0) atomicAdd(&scnt, __popc(bl));
    }
    __syncthreads();
    if (t < 128) {
        g_upart[blockIdx.x * 256 + t] = s0[t] + s0[t + 128] + s0[t + 256] + s0[t + 384];
    } else if (t < 256) {
        int kk = t - 128;
        g_upart[blockIdx.x * 256 + 128 + kk] = s1[kk] + s1[kk + 128] + s1[kk + 256] + s1[kk + 384];
    }
    if (t < 128) { g_Et[row0 + t] = 0.0f; g_E1[row0 + t] = 0.0f; }
    if (t == 0) g_c0part[blockIdx.x] = scnt;
    if (blockIdx.x == 0 && t < out_size) out[t] = 0.0f;
}

// ---- gemm: one CTA = row-block bi, up to 2 column tiles (bj0, bj0+1), bi <= bj
__global__ __launch_bounds__(512) void gemm_kernel(const int* __restrict__ labels) {
    extern __shared__ char smem[];
    const uint32_t sbase = smem_u32(smem);
    float* sred = (float*)(smem + SM_RED);
    const int tid = threadIdx.x;
    const int lane = tid & 31, wid = tid >> 5;
    const int wm = wid >> 2, wn = wid & 3;

    // decode chunk -> (bi, bj0)
    int rem = blockIdx.x, bi = 0;
    while (true) { int w = (65 - bi) >> 1; if (rem < w) break; rem -= w; bi++; }
    const int bj0 = bi + 2 * rem;
    const int ntile = (bj0 + 1 <= 63) ? 2 : 1;
    const int row0 = bi * 128;

    const uint4* fb = (const uint4*)g_featsb;
#pragma unroll
    for (int t = tid; t < 2048; t += 512) {
        int r = t >> 4, q = t & 15;
        *(uint4*)(smem + SM_A + r * SROW + q * 16) = fb[(size_t)(row0 + r) * 16 + q];
    }
    if (bj0 != bi) {   // tile0 B (diag aliases A)
#pragma unroll
        for (int t = tid; t < 2048; t += 512) {
            int r = t >> 4, q = t & 15;
            *(uint4*)(smem + SM_B0 + r * SROW + q * 16) = fb[(size_t)(bj0 * 128 + r) * 16 + q];
        }
    }

    int grow[4], rlab[4];
#pragma unroll
    for (int s = 0; s < 4; s++) {
        grow[s] = row0 + wm * 32 + (s >> 1) * 16 + (lane >> 2) + (s & 1) * 8;
        rlab[s] = labels[grow[s]] != 0;
    }
    const uint32_t a_addr = sbase + SM_A + (wm * 32 + (lane & 15)) * SROW + (lane >> 4) * 16;

    float rEt[4] = {0,0,0,0}, rE1[4] = {0,0,0,0};
    __syncthreads();

    for (int tt = 0; tt < ntile; tt++) {
        const int bj = bj0 + tt;
        const bool isdiag = (bj == bi);
        const int col0 = bj * 128;
        const int cbase = col0 + wn * 32;
        const uint32_t cm = __ballot_sync(0xffffffffu, labels[cbase + lane] != 0);
        const uint32_t b_base = isdiag ? SM_A : (tt == 0 ? SM_B0 : SM_B1);
        const uint32_t b_addr = sbase + b_base + (wn * 32 + (lane & 15)) * SROW + (lane >> 4) * 16;

        float acc[2][4][4];
#pragma unroll
        for (int mt = 0; mt < 2; mt++)
#pragma unroll
            for (int nt = 0; nt < 4; nt++)
#pragma unroll
                for (int i = 0; i < 4; i++) acc[mt][nt][i] = 0.0f;

#pragma unroll
        for (int k = 0; k < 8; k++) {
            uint32_t a[2][4];
            ldmx4(a[0], a_addr + k * 32);
            ldmx4(a[1], a_addr + 16 * SROW + k * 32);
            uint32_t b[4][2];
            {
                uint32_t r4[4];
                ldmx4(r4, b_addr + k * 32);
                b[0][0] = r4[0]; b[1][0] = r4[1]; b[0][1] = r4[2]; b[1][1] = r4[3];
                ldmx4(r4, b_addr + 16 * SROW + k * 32);
                b[2][0] = r4[0]; b[3][0] = r4[1]; b[2][1] = r4[2]; b[3][1] = r4[3];
            }
#pragma unroll
            for (int mt = 0; mt < 2; mt++)
#pragma unroll
                for (int nt = 0; nt < 4; nt++) mma16816(acc[mt][nt], a[mt], b[nt]);
        }

        // prefetch next B tile (distinct smem region; visibility via merge syncs below)
        if (tt == 0 && ntile == 2) {
#pragma unroll
            for (int t = tid; t < 2048; t += 512) {
                int r = t >> 4, q = t & 15;
                *(uint4*)(smem + SM_B1 + r * SROW + q * 16) = fb[(size_t)((bj0 + 1) * 128 + r) * 16 + q];
            }
        }

        // epilogue: exp + E accumulation (row by col-label, col by row-label)
        float cEt[8] = {0,0,0,0,0,0,0,0}, cE1[8] = {0,0,0,0,0,0,0,0};
#pragma unroll
        for (int mt = 0; mt < 2; mt++)
#pragma unroll
            for (int nt = 0; nt < 4; nt++)
#pragma unroll
                for (int idx = 0; idx < 4; idx++) {
                    const int s = mt * 2 + (idx >> 1);
                    const int cs = nt * 2 + (idx & 1);
                    const int crel = nt * 8 + (lane & 3) * 2 + (idx & 1);
                    float ex = ex2f(fmaf(acc[mt][nt][idx], EXS, -EXS));
                    rEt[s] += ex;
                    if ((cm >> crel) & 1) rE1[s] += ex;
                    cEt[cs] += ex;
                    if (rlab[s]) cE1[cs] += ex;
                }

        // column merge (skip global add for diag tile; syncs always run)
        __syncthreads();
        if (tid < 256) sred[tid] = 0.0f;
        __syncthreads();
        if (!isdiag) {
#pragma unroll
            for (int cs = 0; cs < 8; cs++) {
                float vt = cEt[cs], v1 = cE1[cs];
                vt += __shfl_xor_sync(0xffffffffu, vt, 4); vt += __shfl_xor_sync(0xffffffffu, vt, 8); vt += __shfl_xor_sync(0xffffffffu, vt, 16);
                v1 += __shfl_xor_sync(0xffffffffu, v1, 4); v1 += __shfl_xor_sync(0xffffffffu, v1, 8); v1 += __shfl_xor_sync(0xffffffffu, v1, 16);
                if (lane < 4) {
                    int cl = wn * 32 + (cs >> 1) * 8 + lane * 2 + (cs & 1);
                    atomicAdd(&sred[cl], vt);
                    atomicAdd(&sred[128 + cl], v1);
                }
            }
        }
        __syncthreads();
        if (!isdiag) {
            if (tid < 128) atomicAdd(&g_Et[col0 + tid], sred[tid]);
            else if (tid < 256) atomicAdd(&g_E1[col0 + tid - 128], sred[tid]);
        }
    }

    // row merge
    __syncthreads();
    if (tid < 256) sred[tid] = 0.0f;
    __syncthreads();
#pragma unroll
    for (int s = 0; s < 4; s++) {
        float vt = rEt[s], v1 = rE1[s];
        vt += __shfl_xor_sync(0xffffffffu, vt, 1); vt += __shfl_xor_sync(0xffffffffu, vt, 2);
        v1 += __shfl_xor_sync(0xffffffffu, v1, 1); v1 += __shfl_xor_sync(0xffffffffu, v1, 2);
        if ((lane & 3) == 0) {
            int rl = wm * 32 + (s >> 1) * 16 + (lane >> 2) + (s & 1) * 8;
            atomicAdd(&sred[rl], vt);
            atomicAdd(&sred[128 + rl], v1);
        }
    }
    __syncthreads();
    if (tid < 128) atomicAdd(&g_Et[row0 + tid], sred[tid]);
    else if (tid < 256) atomicAdd(&g_E1[row0 + tid - 128], sred[tid]);
}

// ---- finalize: 32 CTAs x 256 threads, one row per thread
__global__ __launch_bounds__(256) void finalize_kernel(const int* __restrict__ labels,
                                                       float* __restrict__ out) {
    __shared__ float su0[128], su1[128];
    __shared__ int sc0;
    __shared__ float sl[256];
    const int t = threadIdx.x;

    if (t < 256) {
        float a = 0.0f;
#pragma unroll 8
        for (int b = 0; b < 64; b++) a += g_upart[b * 256 + t];
        if (t < 128) su0[t] = a; else su1[t - 128] = a;
    }
    if (t == 0) {
        int c = 0;
#pragma unroll
        for (int b = 0; b < 64; b++) c += g_c0part[b];
        sc0 = c;
    }
    __syncthreads();
    const int c0 = sc0;

    const int i = blockIdx.x * 256 + t;
    const int lab = labels[i] != 0;
    const float* u = lab ? su1 : su0;
    const __nv_bfloat162* f = (const __nv_bfloat162*)&g_featsb[(size_t)i * DD];
    float dii = 0.0f, du = 0.0f;
#pragma unroll
    for (int k = 0; k < DD / 2; k++) {
        __nv_bfloat162 p = f[k];
        float a = __bfloat162float(p.x), b = __bfloat162float(p.y);
        dii = fmaf(a, a, dii); dii = fmaf(b, b, dii);
        du = fmaf(a, u[2 * k], du); du = fmaf(b, u[2 * k + 1], du);
    }
    const int nc = lab ? (NN - c0) : c0;
    const float cnt = (float)(nc - 1);
    const float Et = g_Et[i], E1 = g_E1[i];
    const float E0 = Et - E1;
    const float Es = lab ? E1 : E0;     // same-class sum (incl self)
    const float S = lab ? E0 : E1;      // neg sum
    const float lii = fmaf(dii, 10.0f, -10.0f);
    const float P = Es - expf(lii);
    const float L = 10.0f * (du - dii) - 10.0f * cnt;
    const float logden = cnt * logf(S) + P / S;
    float loss = -COEF * (L - logden) / cnt;

    sl[t] = loss;
    __syncthreads();
#pragma unroll
    for (int s = 128; s > 0; s >>= 1) {
        if (t < s) sl[t] += sl[t + s];
        __syncthreads();
    }
    if (t == 0) atomicAdd(out, sl[0] * (1.0f / (float)NN));
}

extern "C" void kernel_launch(void* const* d_in, const int* in_sizes, int n_in,
                              void* d_out, int out_size) {
    const float* feats = (const float*)d_in[0];
    const int* labels = (const int*)d_in[1];
    float* out = (float*)d_out;

    cudaFuncSetAttribute(gemm_kernel, cudaFuncAttributeMaxDynamicSharedMemorySize, SM_TOTAL);

    prep_kernel<<<64, 512>>>(feats, labels, out, out_size);
    gemm_kernel<<<NCHUNK, 512, SM_TOTAL>>>(labels);
    finalize_kernel<<<32, 256>>>(labels, out);
}